// round 12
// baseline (speedup 1.0000x reference)
#include <cuda_runtime.h>
#include <cuda_bf16.h>

#define KDIM 64
#define PF   4   // prefetch depth (steps)

__device__ float g_fwd[1024];
__device__ float g_gold[1024];
__device__ int   g_done = 0;

typedef unsigned long long ull;
template <int N> struct IC { static constexpr int v = N; };

__device__ __forceinline__ void fma2(ull& acc, ull a, ull b) {
    asm("fma.rn.f32x2 %0, %1, %2, %3;" : "=l"(acc) : "l"(a), "l"(b), "l"(acc));
}
__device__ __forceinline__ void add2(ull& d, ull a, ull b) {
    asm("add.rn.f32x2 %0, %1, %2;" : "=l"(d) : "l"(a), "l"(b));
}
__device__ __forceinline__ float sum2(ull v) {
    return __uint_as_float((unsigned)v) + __uint_as_float((unsigned)(v >> 32));
}

// ---------------- gold score: one 256-thread block per batch ----------------
// Direct gather: each thread handles ~T/256 timesteps with independent loads
// (high MLP), then block-reduce. No scratch, no sequential dependence.
__global__ __launch_bounds__(256)
void crf_gold_kernel(const float* __restrict__ emis,
                     const float* __restrict__ trans,
                     const float* __restrict__ start_t,
                     const float* __restrict__ end_t,
                     const int*  __restrict__ labels,
                     const int*  __restrict__ sent_len,
                     int T)
{
    const int b   = blockIdx.x;
    const int tid = threadIdx.x;
    const int L   = sent_len[b];
    const int*   lab = labels + (size_t)b * T;
    const float* em  = emis   + (size_t)b * T * KDIM;

    float s = 0.0f;
    for (int t = tid; t < L; t += 256) {
        const int lt = lab[t];
        float v = em[(size_t)t * KDIM + lt];
        v += (t == 0) ? start_t[lt] : trans[lab[t - 1] * KDIM + lt];
        s += v;
    }
    __shared__ float ws[8];
#pragma unroll
    for (int o = 16; o; o >>= 1) s += __shfl_xor_sync(0xffffffffu, s, o);
    if ((tid & 31) == 0) ws[tid >> 5] = s;
    __syncthreads();
    if (tid < 32) {
        float u = (tid < 8) ? ws[tid] : 0.0f;
#pragma unroll
        for (int o = 4; o; o >>= 1) u += __shfl_xor_sync(0xffffffffu, u, o);
        if (tid == 0) g_gold[b] = u + end_t[lab[L - 1]];
    }
}

// ---------------- forward: TWO batches per warp, NO gold state ----------------
// Batches (blockIdx.x, blockIdx.x + B/2) share the E = exp(trans) register set
// (64 f32x2 pairs = 128 regs, paid once). Lane l owns columns j0=2l, j1=2l+1
// of both batches; the two independent recursions interleave so each hides the
// other's STS->LDS->FMA-tree boundary latency. Linear-space recursion with
// exact power-of-2 renorm. Emission ring holds RAW loads (PF steps deep).
__global__ __launch_bounds__(32, 1)
void crf_forward2(const float* __restrict__ emis,
                  const float* __restrict__ trans,
                  const float* __restrict__ start_t,
                  const float* __restrict__ end_t,
                  const int*  __restrict__ sent_len,
                  int T, int B, float* __restrict__ out)
{
    const int lane = threadIdx.x;
    const int j0   = 2 * lane;
    const int j1   = j0 + 1;
    const int half = B >> 1;
    const int bid0 = blockIdx.x;
    const int bid1 = blockIdx.x + half;

    const float* em[2];
    em[0] = emis + (size_t)bid0 * T * KDIM;
    em[1] = emis + (size_t)bid1 * T * KDIM;
    int L[2];
    L[0] = sent_len[bid0];
    L[1] = sent_len[bid1];

    __shared__ __align__(16) float sa[2][2][KDIM];   // [batch][buf][state]

    // shared E registers
    ull Epk0[KDIM / 2], Epk1[KDIM / 2];
#pragma unroll
    for (int i2 = 0; i2 < KDIM / 2; ++i2) {
        const float a00 = __expf(trans[(2 * i2)     * KDIM + j0]);
        const float a10 = __expf(trans[(2 * i2 + 1) * KDIM + j0]);
        const float a01 = __expf(trans[(2 * i2)     * KDIM + j1]);
        const float a11 = __expf(trans[(2 * i2 + 1) * KDIM + j1]);
        Epk0[i2] = (ull)__float_as_uint(a00) | ((ull)__float_as_uint(a10) << 32);
        Epk1[i2] = (ull)__float_as_uint(a01) | ((ull)__float_as_uint(a11) << 32);
    }

    // per-batch state (no gold!)
    float ax[2], ay[2];
    int   Stot[2];
    float2 er[2][PF];

    const float2 st = ((const float2*)start_t)[lane];
#pragma unroll
    for (int s = 0; s < 2; ++s) {
        const float2 e0 = ((const float2*)em[s])[lane];
        ax[s] = __expf(st.x + e0.x);
        ay[s] = __expf(st.y + e0.y);
        Stot[s] = 0;
#pragma unroll
        for (int k = 0; k < PF; ++k) {
            int tt = 1 + k; if (tt > T - 1) tt = T - 1;
            er[s][k] = ((const float2*)(em[s] + (size_t)tt * KDIM))[lane];
        }
    }

    int buf = 0;
    const int Lmin = (L[0] < L[1]) ? L[0] : L[1];

    // ---------------- fused main loop: both batches per step ----------------
    int t = 1;
    for (; t + PF <= Lmin; t += PF) {
#pragma unroll
        for (int k = 0; k < PF; ++k) {
            float2 ec[2];
#pragma unroll
            for (int s = 0; s < 2; ++s) {
                ec[s] = er[s][k];
                int tp = t + PF + k; if (tp > T - 1) tp = T - 1;
                er[s][k] = ((const float2*)(em[s] + (size_t)tp * KDIM))[lane];
            }
            // consume-time exps + STS (both batches)
            float Px[2], Py[2];
#pragma unroll
            for (int s = 0; s < 2; ++s) {
                Px[s] = __expf(ec[s].x);
                Py[s] = __expf(ec[s].y);
                ((float2*)sa[s][buf])[lane] = make_float2(ax[s], ay[s]);
            }
            asm volatile("" ::: "memory");
            const ulonglong2* sv0 = (const ulonglong2*)sa[0][buf];
            const ulonglong2* sv1 = (const ulonglong2*)sa[1][buf];
            ull p0[2], p1[2], q0[2], q1[2];
            float scl[2];
            {
                ulonglong2 v00[2], v01[2];
                v00[0] = sv0[0]; v01[0] = sv0[1];
                v00[1] = sv1[0]; v01[1] = sv1[1];
#pragma unroll
                for (int s = 0; s < 2; ++s) {
                    const unsigned pb = (unsigned)v00[s].x;          // sa[s][buf][0]
                    const int e = (int)((pb >> 23) & 0xffu);
                    scl[s] = __uint_as_float((unsigned)(254 - e) << 23);
                    Stot[s] += e - 127;
                    p0[s] = p1[s] = q0[s] = q1[s] = 0ull;
                    fma2(p0[s], v00[s].x, Epk0[0]);  fma2(q0[s], v00[s].x, Epk1[0]);
                    fma2(p1[s], v00[s].y, Epk0[1]);  fma2(q1[s], v00[s].y, Epk1[1]);
                    fma2(p0[s], v01[s].x, Epk0[2]);  fma2(q0[s], v01[s].x, Epk1[2]);
                    fma2(p1[s], v01[s].y, Epk0[3]);  fma2(q1[s], v01[s].y, Epk1[3]);
                }
            }
#pragma unroll
            for (int q = 1; q < 8; ++q) {
                ulonglong2 w0[2], w1[2];
                w0[0] = sv0[2 * q]; w1[0] = sv0[2 * q + 1];
                w0[1] = sv1[2 * q]; w1[1] = sv1[2 * q + 1];
#pragma unroll
                for (int s = 0; s < 2; ++s) {
                    fma2(p0[s], w0[s].x, Epk0[4 * q + 0]);  fma2(q0[s], w0[s].x, Epk1[4 * q + 0]);
                    fma2(p1[s], w0[s].y, Epk0[4 * q + 1]);  fma2(q1[s], w0[s].y, Epk1[4 * q + 1]);
                    fma2(p0[s], w1[s].x, Epk0[4 * q + 2]);  fma2(q0[s], w1[s].x, Epk1[4 * q + 2]);
                    fma2(p1[s], w1[s].y, Epk0[4 * q + 3]);  fma2(q1[s], w1[s].y, Epk1[4 * q + 3]);
                }
            }
#pragma unroll
            for (int s = 0; s < 2; ++s) {
                add2(p0[s], p0[s], p1[s]);
                add2(q0[s], q0[s], q1[s]);
                ax[s] = sum2(p0[s]) * scl[s] * Px[s];
                ay[s] = sum2(q0[s]) * scl[s] * Py[s];
            }
            buf ^= 1;
        }
    }

    // ---------------- solo loops: finish each batch independently ----------------
    auto runSolo = [&](auto S) {
        constexpr int s = decltype(S)::v;
        int sbuf = buf;
        auto soloStep = [&](float2 s_ec) {
            const float Px = __expf(s_ec.x);
            const float Py = __expf(s_ec.y);
            ((float2*)sa[s][sbuf])[lane] = make_float2(ax[s], ay[s]);
            asm volatile("" ::: "memory");
            const ulonglong2* sv = (const ulonglong2*)sa[s][sbuf];
            const ulonglong2 v00 = sv[0];
            const ulonglong2 v01 = sv[1];
            const unsigned pb = (unsigned)v00.x;
            const int e = (int)((pb >> 23) & 0xffu);
            const float scl = __uint_as_float((unsigned)(254 - e) << 23);
            Stot[s] += e - 127;
            ull a0 = 0ull, a1 = 0ull, c0 = 0ull, c1 = 0ull;
            fma2(a0, v00.x, Epk0[0]);  fma2(c0, v00.x, Epk1[0]);
            fma2(a1, v00.y, Epk0[1]);  fma2(c1, v00.y, Epk1[1]);
            fma2(a0, v01.x, Epk0[2]);  fma2(c0, v01.x, Epk1[2]);
            fma2(a1, v01.y, Epk0[3]);  fma2(c1, v01.y, Epk1[3]);
#pragma unroll
            for (int q = 1; q < 8; ++q) {
                const ulonglong2 w0 = sv[2 * q];
                const ulonglong2 w1 = sv[2 * q + 1];
                fma2(a0, w0.x, Epk0[4 * q + 0]);  fma2(c0, w0.x, Epk1[4 * q + 0]);
                fma2(a1, w0.y, Epk0[4 * q + 1]);  fma2(c1, w0.y, Epk1[4 * q + 1]);
                fma2(a0, w1.x, Epk0[4 * q + 2]);  fma2(c0, w1.x, Epk1[4 * q + 2]);
                fma2(a1, w1.y, Epk0[4 * q + 3]);  fma2(c1, w1.y, Epk1[4 * q + 3]);
            }
            add2(a0, a0, a1);
            add2(c0, c0, c1);
            ax[s] = sum2(a0) * scl * Px;
            ay[s] = sum2(c0) * scl * Py;
            sbuf ^= 1;
        };
        int ts = t;
        for (; ts + PF <= L[s]; ts += PF) {
#pragma unroll
            for (int k = 0; k < PF; ++k) {
                const float2 ec2 = er[s][k];
                int tp = ts + PF + k; if (tp > T - 1) tp = T - 1;
                er[s][k] = ((const float2*)(em[s] + (size_t)tp * KDIM))[lane];
                soloStep(ec2);
            }
        }
        for (int k = 0; ts < L[s]; ++ts, ++k)
            soloStep(er[s][k]);
    };
    runSolo(IC<0>{});
    runSolo(IC<1>{});

    // ---------------- finalize both batches ----------------
    const float2 en = ((const float2*)end_t)[lane];
    const float enx = __expf(en.x);
    const float eny = __expf(en.y);
#pragma unroll
    for (int s = 0; s < 2; ++s) {
        float xs = ax[s] * enx + ay[s] * eny;
#pragma unroll
        for (int o = 16; o; o >>= 1)
            xs += __shfl_xor_sync(0xffffffffu, xs, o);
        if (lane == 0)
            g_fwd[(s == 0) ? bid0 : bid1] =
                __logf(xs) + (float)Stot[s] * 0.69314718055994530942f;
    }

    // ---------------- finisher: last block reduces all partials ----------------
    __threadfence();
    int isLast = 0;
    if (lane == 0) {
        const int old = atomicAdd(&g_done, 1);
        isLast = (old == half - 1);
    }
    isLast = __shfl_sync(0xffffffffu, isLast, 0);
    if (isLast) {
        __threadfence();
        float v = 0.0f;
        for (int i = lane; i < B; i += 32) v += g_fwd[i] - g_gold[i];
#pragma unroll
        for (int o = 16; o; o >>= 1) v += __shfl_xor_sync(0xffffffffu, v, o);
        if (lane == 0) {
            out[0] = v / (float)B;
            g_done = 0;
        }
    }
}

extern "C" void kernel_launch(void* const* d_in, const int* in_sizes, int n_in,
                              void* d_out, int out_size)
{
    const float* emis    = (const float*)d_in[0];
    const float* trans   = (const float*)d_in[1];
    const float* start_t = (const float*)d_in[2];
    const float* end_t   = (const float*)d_in[3];
    const int*   labels  = (const int*)d_in[4];
    const int*   slen    = (const int*)d_in[5];

    const int B = in_sizes[5];            // 512
    const int T = in_sizes[4] / B;        // 1024
    float* out = (float*)d_out;

    crf_gold_kernel<<<B, 256>>>(emis, trans, start_t, end_t, labels, slen, T);
    crf_forward2<<<B / 2, 32>>>(emis, trans, start_t, end_t, slen, T, B, out);
}

// round 13
// speedup vs baseline: 1.8926x; 1.8926x over previous
#include <cuda_runtime.h>
#include <cuda_bf16.h>

#define KDIM 64
#define PF   4   // prefetch depth (steps)

__device__ float g_fwd[1024];
__device__ float g_gold[1024];
__device__ int   g_done = 0;

typedef unsigned long long ull;

__device__ __forceinline__ void fma2(ull& acc, ull a, ull b) {
    asm("fma.rn.f32x2 %0, %1, %2, %3;" : "=l"(acc) : "l"(a), "l"(b), "l"(acc));
}
__device__ __forceinline__ void add2(ull& d, ull a, ull b) {
    asm("add.rn.f32x2 %0, %1, %2;" : "=l"(d) : "l"(a), "l"(b));
}
__device__ __forceinline__ float sum2(ull v) {
    return __uint_as_float((unsigned)v) + __uint_as_float((unsigned)(v >> 32));
}

// ---------------- gold score: one 256-thread block per batch ----------------
__global__ __launch_bounds__(256)
void crf_gold_kernel(const float* __restrict__ emis,
                     const float* __restrict__ trans,
                     const float* __restrict__ start_t,
                     const float* __restrict__ end_t,
                     const int*  __restrict__ labels,
                     const int*  __restrict__ sent_len,
                     int T)
{
    const int b   = blockIdx.x;
    const int tid = threadIdx.x;
    const int L   = sent_len[b];
    const int*   lab = labels + (size_t)b * T;
    const float* em  = emis   + (size_t)b * T * KDIM;

    float s = 0.0f;
    for (int t = tid; t < L; t += 256) {
        const int lt = lab[t];
        float v = em[(size_t)t * KDIM + lt];
        v += (t == 0) ? start_t[lt] : trans[lab[t - 1] * KDIM + lt];
        s += v;
    }
    __shared__ float ws[8];
#pragma unroll
    for (int o = 16; o; o >>= 1) s += __shfl_xor_sync(0xffffffffu, s, o);
    if ((tid & 31) == 0) ws[tid >> 5] = s;
    __syncthreads();
    if (tid < 32) {
        float u = (tid < 8) ? ws[tid] : 0.0f;
#pragma unroll
        for (int o = 4; o; o >>= 1) u += __shfl_xor_sync(0xffffffffu, u, o);
        if (tid == 0) g_gold[b] = u + end_t[lab[L - 1]];
    }
}

// ---------------- forward: 64 THREADS (2 warps) per batch ----------------
// Thread j owns CRF column j. Per-warp FMA stream is HALF of the 32-thread
// version (32 fma2); one __syncthreads per step (double-buffered sa). With
// 512 blocks x 2 warps, ~1.75 warps/SMSP co-residency hides residual stalls.
// Linear-space recursion with exact power-of-2 renorm; emission ring holds
// RAW loads (exp at consume time). No gold work here (separate kernel).
__global__ __launch_bounds__(64, 1)
void crf_forward64(const float* __restrict__ emis,
                   const float* __restrict__ trans,
                   const float* __restrict__ start_t,
                   const float* __restrict__ end_t,
                   const int*  __restrict__ sent_len,
                   int T, int B, float* __restrict__ out)
{
    const int b = blockIdx.x;
    const int j = threadIdx.x;
    const int L = sent_len[b];
    const float* em = emis + (size_t)b * T * KDIM;

    __shared__ __align__(16) float sa[2][KDIM];
    __shared__ float rsum[2];
    __shared__ int   sh_last;

    // E column j as 32 packed (i, i+1) f32x2 pairs -> 64 regs
    ull Epk[KDIM / 2];
#pragma unroll
    for (int i2 = 0; i2 < KDIM / 2; ++i2) {
        const float lo = __expf(trans[(2 * i2)     * KDIM + j]);
        const float hi = __expf(trans[(2 * i2 + 1) * KDIM + j]);
        Epk[i2] = (ull)__float_as_uint(lo) | ((ull)__float_as_uint(hi) << 32);
    }

    // t = 0
    float a = __expf(start_t[j] + em[j]);
    int   Stot = 0;

    // raw emission ring for steps t = 1..PF
    float er[PF];
#pragma unroll
    for (int k = 0; k < PF; ++k) {
        int tt = 1 + k; if (tt > T - 1) tt = T - 1;
        er[k] = em[(size_t)tt * KDIM + j];
    }

    int buf = 0;
    auto step = [&](float eraw) {
        const float P = __expf(eraw);      // consume-time exp (loaded PF ago)
        sa[buf][j] = a;
        __syncthreads();
        const ulonglong2* sv = (const ulonglong2*)sa[buf];
        const ulonglong2 v0 = sv[0];
        const ulonglong2 v1 = sv[1];
        const unsigned pb = (unsigned)v0.x;                  // sa[buf][0]
        const int e = (int)((pb >> 23) & 0xffu);
        const float scl = __uint_as_float((unsigned)(254 - e) << 23); // 2^(127-e)
        Stot += e - 127;
        ull a0 = 0ull, a1 = 0ull, a2 = 0ull, a3 = 0ull;
        fma2(a0, v0.x, Epk[0]);
        fma2(a1, v0.y, Epk[1]);
        fma2(a2, v1.x, Epk[2]);
        fma2(a3, v1.y, Epk[3]);
#pragma unroll
        for (int q = 1; q < 8; ++q) {
            const ulonglong2 w0 = sv[2 * q];
            const ulonglong2 w1 = sv[2 * q + 1];
            fma2(a0, w0.x, Epk[4 * q + 0]);
            fma2(a1, w0.y, Epk[4 * q + 1]);
            fma2(a2, w1.x, Epk[4 * q + 2]);
            fma2(a3, w1.y, Epk[4 * q + 3]);
        }
        add2(a0, a0, a1);
        add2(a2, a2, a3);
        add2(a0, a0, a2);
        a = sum2(a0) * scl * P;
        buf ^= 1;
    };

    int t = 1;
    for (; t + PF <= L; t += PF) {
#pragma unroll
        for (int k = 0; k < PF; ++k) {
            const float ec = er[k];
            int tp = t + PF + k; if (tp > T - 1) tp = T - 1;
            er[k] = em[(size_t)tp * KDIM + j];   // raw deep prefetch
            step(ec);
        }
    }
    for (int k = 0; t < L; ++t, ++k)             // tail: ring already filled
        step(er[k]);

    // fwd = log( sum_j a[j]*exp(end[j]) ) + Stot*ln2  (Stot uniform per block)
    {
        float xs = a * __expf(end_t[j]);
#pragma unroll
        for (int o = 16; o; o >>= 1)
            xs += __shfl_xor_sync(0xffffffffu, xs, o);
        if ((j & 31) == 0) rsum[j >> 5] = xs;
        __syncthreads();
        if (j == 0)
            g_fwd[b] = __logf(rsum[0] + rsum[1])
                     + (float)Stot * 0.69314718055994530942f;
    }

    // ---------------- finisher: last block reduces all partials ----------------
    if (j == 0) {
        __threadfence();
        const int old = atomicAdd(&g_done, 1);
        sh_last = (old == gridDim.x - 1);
    }
    __syncthreads();
    if (sh_last) {
        __threadfence();
        float v = 0.0f;
        for (int i = j; i < B; i += 64) v += g_fwd[i] - g_gold[i];
#pragma unroll
        for (int o = 16; o; o >>= 1) v += __shfl_xor_sync(0xffffffffu, v, o);
        if ((j & 31) == 0) rsum[j >> 5] = v;
        __syncthreads();
        if (j == 0) {
            out[0] = (rsum[0] + rsum[1]) / (float)B;
            g_done = 0;                    // reset for next (deterministic) call
        }
    }
}

extern "C" void kernel_launch(void* const* d_in, const int* in_sizes, int n_in,
                              void* d_out, int out_size)
{
    const float* emis    = (const float*)d_in[0];
    const float* trans   = (const float*)d_in[1];
    const float* start_t = (const float*)d_in[2];
    const float* end_t   = (const float*)d_in[3];
    const int*   labels  = (const int*)d_in[4];
    const int*   slen    = (const int*)d_in[5];

    const int B = in_sizes[5];            // 512
    const int T = in_sizes[4] / B;        // 1024
    float* out = (float*)d_out;

    crf_gold_kernel<<<B, 256>>>(emis, trans, start_t, end_t, labels, slen, T);
    crf_forward64<<<B, 64>>>(emis, trans, start_t, end_t, slen, T, B, out);
}